// round 1
// baseline (speedup 1.0000x reference)
#include <cuda_runtime.h>
#include <math.h>

#define H   1024
#define H2  2048
#define H3  3072
#define SS  4096
#define V   50257

// ---- scratch (no allocations allowed) ----
__device__ float g_x[H2];          // [emb, last_context]
__device__ float g_gi[H3];
__device__ float g_gh[H3];
__device__ float g_hnew[H];
__device__ float g_scores[SS];
__device__ float g_attn[SS];
__device__ float g_y[H2];          // [h_new, context]
__device__ float g_cpart[32 * H];  // context partials (deterministic 2-stage reduce)
__device__ float g_logits[V + 16];
__device__ float g_red[2];         // max, log(sumexp)

// output layout (tuple order): output[V], context[H], h_new[H], attn[S]
#define OUT_OUTPUT  0
#define OUT_CONTEXT (V)
#define OUT_HNEW    (V + H)
#define OUT_ATTN    (V + 2 * H)

__device__ __forceinline__ float warpReduceSum(float v) {
    #pragma unroll
    for (int o = 16; o > 0; o >>= 1) v += __shfl_down_sync(0xffffffffu, v, o);
    return v;
}
__device__ __forceinline__ float warpReduceMax(float v) {
    #pragma unroll
    for (int o = 16; o > 0; o >>= 1) v = fmaxf(v, __shfl_down_sync(0xffffffffu, v, o));
    return v;
}

// K0: x = [embedding[word], last_context]
__global__ void k_buildx(const int* __restrict__ word,
                         const float* __restrict__ emb,
                         const float* __restrict__ ctx) {
    int i = blockIdx.x * blockDim.x + threadIdx.x;
    if (i < H)        g_x[i] = emb[(size_t)word[0] * H + i];
    else if (i < H2)  g_x[i] = ctx[i - H];
}

// K1: gi = w_ih@x + b_ih ; gh = w_hh@h + b_hh. One block per output row.
__global__ void k_gates(const float* __restrict__ w_ih,
                        const float* __restrict__ w_hh,
                        const float* __restrict__ b_ih,
                        const float* __restrict__ b_hh,
                        const float* __restrict__ h) {
    int b = blockIdx.x;
    const float4* w4;
    const float4* v4;
    int n4;
    float bias;
    float* dst;
    if (b < H3) {
        w4 = (const float4*)(w_ih + (size_t)b * H2);
        v4 = (const float4*)g_x;
        n4 = H2 / 4; bias = b_ih[b]; dst = &g_gi[b];
    } else {
        int r = b - H3;
        w4 = (const float4*)(w_hh + (size_t)r * H);
        v4 = (const float4*)h;
        n4 = H / 4; bias = b_hh[r]; dst = &g_gh[r];
    }
    float acc = 0.f;
    for (int j = threadIdx.x; j < n4; j += blockDim.x) {
        float4 a = w4[j], c = v4[j];
        acc += a.x * c.x + a.y * c.y + a.z * c.z + a.w * c.w;
    }
    __shared__ float sred[8];
    float r = warpReduceSum(acc);
    int wid = threadIdx.x >> 5, lane = threadIdx.x & 31;
    if (lane == 0) sred[wid] = r;
    __syncthreads();
    if (wid == 0) {
        r = (lane < (blockDim.x >> 5)) ? sred[lane] : 0.f;
        r = warpReduceSum(r);
        if (lane == 0) *dst = r + bias;
    }
}

// K2: GRU pointwise -> h_new. Also writes h_new output slot and y[0:H].
__global__ void k_hnew(const float* __restrict__ h, float* __restrict__ out) {
    int i = threadIdx.x;  // 1024 threads
    float r = 1.f / (1.f + expf(-(g_gi[i]       + g_gh[i])));
    float z = 1.f / (1.f + expf(-(g_gi[H + i]   + g_gh[H + i])));
    float n = tanhf(g_gi[2 * H + i] + r * g_gh[2 * H + i]);
    float hn = (1.f - z) * n + z * h[i];
    g_hnew[i] = hn;
    g_y[i] = hn;
    out[OUT_HNEW + i] = hn;
}

// K3: scores[s] = enc[s] . h_new. One block per s.
__global__ void k_scores(const float* __restrict__ enc) {
    int s = blockIdx.x;
    const float4* e4 = (const float4*)(enc + (size_t)s * H);
    const float4* h4 = (const float4*)g_hnew;
    float acc = 0.f;
    for (int j = threadIdx.x; j < H / 4; j += blockDim.x) {
        float4 a = e4[j], c = h4[j];
        acc += a.x * c.x + a.y * c.y + a.z * c.z + a.w * c.w;
    }
    __shared__ float sred[8];
    float r = warpReduceSum(acc);
    int wid = threadIdx.x >> 5, lane = threadIdx.x & 31;
    if (lane == 0) sred[wid] = r;
    __syncthreads();
    if (wid == 0) {
        r = (lane < (blockDim.x >> 5)) ? sred[lane] : 0.f;
        r = warpReduceSum(r);
        if (lane == 0) g_scores[s] = r;
    }
}

// K4: softmax over S=4096 (single block, 1024 threads). Writes attn output slot.
__global__ void k_softmax(float* __restrict__ out) {
    __shared__ float sred[32];
    __shared__ float sM, sSum;
    int tid = threadIdx.x;
    int wid = tid >> 5, lane = tid & 31;

    float m = -1e30f;
    for (int i = tid; i < SS; i += 1024) m = fmaxf(m, g_scores[i]);
    m = warpReduceMax(m);
    if (lane == 0) sred[wid] = m;
    __syncthreads();
    if (wid == 0) {
        m = (lane < 32) ? sred[lane] : -1e30f;
        m = warpReduceMax(m);
        if (lane == 0) sM = m;
    }
    __syncthreads();
    float M = sM;

    float s = 0.f;
    for (int i = tid; i < SS; i += 1024) s += expf(g_scores[i] - M);
    s = warpReduceSum(s);
    if (lane == 0) sred[wid] = s;
    __syncthreads();
    if (wid == 0) {
        s = (lane < 32) ? sred[lane] : 0.f;
        s = warpReduceSum(s);
        if (lane == 0) sSum = s;
    }
    __syncthreads();
    float inv = 1.f / sSum;

    for (int i = tid; i < SS; i += 1024) {
        float a = expf(g_scores[i] - M) * inv;
        g_attn[i] = a;
        out[OUT_ATTN + i] = a;
    }
}

// K5a: context partials. grid (4 col-groups, 32 s-chunks), 256 threads.
__global__ void k_ctx_part(const float* __restrict__ enc) {
    int col = blockIdx.x * 256 + threadIdx.x;
    int s0 = blockIdx.y * 128;
    float acc = 0.f;
    #pragma unroll 8
    for (int s = s0; s < s0 + 128; s++)
        acc += g_attn[s] * enc[(size_t)s * H + col];
    g_cpart[blockIdx.y * H + col] = acc;
}

// K5b: sum the 32 partials per column (deterministic). Writes context + y[H:2H].
__global__ void k_ctx_sum(float* __restrict__ out) {
    int col = threadIdx.x;  // 1024 threads
    float acc = 0.f;
    #pragma unroll
    for (int p = 0; p < 32; p++) acc += g_cpart[p * H + col];
    out[OUT_CONTEXT + col] = acc;
    g_y[H + col] = acc;
}

// K6: logits = out_w @ y + out_b. Warp per row, y staged in smem. THE hot kernel.
__global__ void __launch_bounds__(256) k_logits(const float* __restrict__ out_w,
                                                const float* __restrict__ out_b) {
    __shared__ float4 sy[H2 / 4];
    for (int j = threadIdx.x; j < H2 / 4; j += blockDim.x)
        sy[j] = ((const float4*)g_y)[j];
    __syncthreads();

    int warp = threadIdx.x >> 5, lane = threadIdx.x & 31;
    int row = blockIdx.x * 8 + warp;
    if (row >= V) return;  // whole warp exits together

    const float4* w4 = (const float4*)(out_w + (size_t)row * H2);
    float acc = 0.f;
    #pragma unroll
    for (int j = lane; j < H2 / 4; j += 32) {
        float4 a = w4[j], y = sy[j];
        acc += a.x * y.x + a.y * y.y + a.z * y.z + a.w * y.w;
    }
    acc = warpReduceSum(acc);
    if (lane == 0) g_logits[row] = acc + out_b[row];
}

// K7: log-softmax reduction (single block, 1024 threads).
__global__ void k_lsm_red() {
    __shared__ float sred[32];
    __shared__ float sM, sSum;
    int tid = threadIdx.x;
    int wid = tid >> 5, lane = tid & 31;

    float m = -1e30f;
    for (int i = tid; i < V; i += 1024) m = fmaxf(m, g_logits[i]);
    m = warpReduceMax(m);
    if (lane == 0) sred[wid] = m;
    __syncthreads();
    if (wid == 0) {
        m = (lane < 32) ? sred[lane] : -1e30f;
        m = warpReduceMax(m);
        if (lane == 0) sM = m;
    }
    __syncthreads();
    float M = sM;

    float s = 0.f;
    for (int i = tid; i < V; i += 1024) s += expf(g_logits[i] - M);
    s = warpReduceSum(s);
    if (lane == 0) sred[wid] = s;
    __syncthreads();
    if (wid == 0) {
        s = (lane < 32) ? sred[lane] : 0.f;
        s = warpReduceSum(s);
        if (lane == 0) sSum = s;
    }
    __syncthreads();
    if (tid == 0) { g_red[0] = M; g_red[1] = logf(sSum); }
}

// K8: output = logits - max - log(sumexp)
__global__ void k_lsm_write(float* __restrict__ out) {
    int i = blockIdx.x * blockDim.x + threadIdx.x;
    if (i < V) out[OUT_OUTPUT + i] = g_logits[i] - g_red[0] - g_red[1];
}

extern "C" void kernel_launch(void* const* d_in, const int* in_sizes, int n_in,
                              void* d_out, int out_size) {
    const int*   word         = (const int*)d_in[0];
    const float* last_context = (const float*)d_in[1];
    const float* last_hidden  = (const float*)d_in[2];
    const float* enc          = (const float*)d_in[3];
    const float* embedding    = (const float*)d_in[4];
    const float* w_ih         = (const float*)d_in[5];
    const float* w_hh         = (const float*)d_in[6];
    const float* b_ih         = (const float*)d_in[7];
    const float* b_hh         = (const float*)d_in[8];
    const float* out_w        = (const float*)d_in[9];
    const float* out_b        = (const float*)d_in[10];
    float* out = (float*)d_out;

    k_buildx  <<<(H2 + 255) / 256, 256>>>(word, embedding, last_context);
    k_gates   <<<2 * H3, 256>>>(w_ih, w_hh, b_ih, b_hh, last_hidden);
    k_hnew    <<<1, H>>>(last_hidden, out);
    k_scores  <<<SS, 256>>>(enc);
    k_softmax <<<1, 1024>>>(out);
    k_ctx_part<<<dim3(H / 256, 32), 256>>>(enc);
    k_ctx_sum <<<1, H>>>(out);
    k_logits  <<<(V + 7) / 8, 256>>>(out_w, out_b);
    k_lsm_red <<<1, 1024>>>();
    k_lsm_write<<<(V + 255) / 256, 256>>>(out);
}

// round 2
// speedup vs baseline: 1.1322x; 1.1322x over previous
#include <cuda_runtime.h>
#include <math.h>

#define H   1024
#define H2  2048
#define H3  3072
#define SS  4096
#define V   50257

// ---- scratch (no allocations allowed) ----
__device__ float g_gi[H3];
__device__ float g_gh[H3];
__device__ float g_scores[SS];
__device__ float g_attn[SS];
__device__ float g_y[H2];          // [h_new, context]
__device__ float g_cpart[32 * H];  // context partials (deterministic 2-stage reduce)
__device__ float g_logits[V + 16];
__device__ float g_red[2];         // max, log(sumexp)

// output layout (tuple order): output[V], context[H], h_new[H], attn[S]
#define OUT_OUTPUT  0
#define OUT_CONTEXT (V)
#define OUT_HNEW    (V + H)
#define OUT_ATTN    (V + 2 * H)

__device__ __forceinline__ float warpReduceSum(float v) {
    #pragma unroll
    for (int o = 16; o > 0; o >>= 1) v += __shfl_down_sync(0xffffffffu, v, o);
    return v;
}
__device__ __forceinline__ float warpReduceMax(float v) {
    #pragma unroll
    for (int o = 16; o > 0; o >>= 1) v = fmaxf(v, __shfl_down_sync(0xffffffffu, v, o));
    return v;
}
__device__ __forceinline__ float dot4(float4 a, float4 b) {
    return a.x * b.x + a.y * b.y + a.z * b.z + a.w * b.w;
}

// K1: gi = w_ih@[emb,ctx] + b_ih ; gh = w_hh@h + b_hh.
// Warp-per-row, 8 rows/block. Blocks [0,384): w_ih rows. Blocks [384,768): w_hh rows.
// x (or h) staged in smem; buildx fused (emb row + ctx loaded directly).
__global__ void __launch_bounds__(256) k_gates(
        const int* __restrict__ word,
        const float* __restrict__ emb,
        const float* __restrict__ ctx,
        const float* __restrict__ w_ih,
        const float* __restrict__ w_hh,
        const float* __restrict__ b_ih,
        const float* __restrict__ b_hh,
        const float* __restrict__ h) {
    __shared__ float4 sv[H2 / 4];   // 8KB max
    int b = blockIdx.x;
    int tid = threadIdx.x;
    bool ih = (b < 384);
    if (ih) {
        const float4* e4 = (const float4*)(emb + (size_t)word[0] * H);
        sv[tid] = e4[tid];                                   // x[0:1024]
        sv[256 + tid] = ((const float4*)ctx)[tid];           // x[1024:2048]
    } else {
        sv[tid] = ((const float4*)h)[tid];                   // h[0:1024]
    }
    __syncthreads();

    int warp = tid >> 5, lane = tid & 31;
    if (ih) {
        int row = b * 8 + warp;
        const float4* w4 = (const float4*)(w_ih + (size_t)row * H2);
        float acc = 0.f;
        #pragma unroll
        for (int i = 0; i < 16; i++) {
            int j = lane + 32 * i;
            acc += dot4(__ldcs(w4 + j), sv[j]);
        }
        acc = warpReduceSum(acc);
        if (lane == 0) g_gi[row] = acc + b_ih[row];
    } else {
        int row = (b - 384) * 8 + warp;
        const float4* w4 = (const float4*)(w_hh + (size_t)row * H);
        float acc = 0.f;
        #pragma unroll
        for (int i = 0; i < 8; i++) {
            int j = lane + 32 * i;
            acc += dot4(__ldcs(w4 + j), sv[j]);
        }
        acc = warpReduceSum(acc);
        if (lane == 0) g_gh[row] = acc + b_hh[row];
    }
}

// K2: fused GRU pointwise (h_new, recomputed per block into smem) + attention
// scores. Warp-per-row, 8 rows/block, 512 blocks. Block 0 also writes h_new
// outputs (g_y[0:H], out h_new slot).
__global__ void __launch_bounds__(256) k_scores(
        const float* __restrict__ enc,
        const float* __restrict__ h,
        float* __restrict__ out) {
    __shared__ float4 sh[H / 4];
    int tid = threadIdx.x;
    for (int i = tid; i < H; i += 256) {
        float r = 1.f / (1.f + expf(-(g_gi[i]     + g_gh[i])));
        float z = 1.f / (1.f + expf(-(g_gi[H + i] + g_gh[H + i])));
        float n = tanhf(g_gi[2 * H + i] + r * g_gh[2 * H + i]);
        float hn = (1.f - z) * n + z * h[i];
        ((float*)sh)[i] = hn;
        if (blockIdx.x == 0) {
            g_y[i] = hn;
            out[OUT_HNEW + i] = hn;
        }
    }
    __syncthreads();

    int warp = tid >> 5, lane = tid & 31;
    int row = blockIdx.x * 8 + warp;
    const float4* e4 = (const float4*)(enc + (size_t)row * H);
    float acc = 0.f;
    #pragma unroll
    for (int i = 0; i < 8; i++) {
        int j = lane + 32 * i;
        acc += dot4(e4[j], sh[j]);
    }
    acc = warpReduceSum(acc);
    if (lane == 0) g_scores[row] = acc;
}

// K3: softmax over S=4096 (single block). Writes attn output slot.
__global__ void k_softmax(float* __restrict__ out) {
    __shared__ float sred[32];
    __shared__ float sM, sSum;
    int tid = threadIdx.x;
    int wid = tid >> 5, lane = tid & 31;

    float m = -1e30f;
    for (int i = tid; i < SS; i += 1024) m = fmaxf(m, g_scores[i]);
    m = warpReduceMax(m);
    if (lane == 0) sred[wid] = m;
    __syncthreads();
    if (wid == 0) {
        m = sred[lane];
        m = warpReduceMax(m);
        if (lane == 0) sM = m;
    }
    __syncthreads();
    float M = sM;

    float s = 0.f;
    for (int i = tid; i < SS; i += 1024) s += expf(g_scores[i] - M);
    s = warpReduceSum(s);
    if (lane == 0) sred[wid] = s;
    __syncthreads();
    if (wid == 0) {
        s = sred[lane];
        s = warpReduceSum(s);
        if (lane == 0) sSum = s;
    }
    __syncthreads();
    float inv = 1.f / sSum;

    for (int i = tid; i < SS; i += 1024) {
        float a = expf(g_scores[i] - M) * inv;
        g_attn[i] = a;
        out[OUT_ATTN + i] = a;
    }
}

// K4a: context partials. grid (4 col-groups, 32 s-chunks), 256 threads.
// enc is L2-resident after k_scores.
__global__ void __launch_bounds__(256) k_ctx_part(const float* __restrict__ enc) {
    int col = blockIdx.x * 256 + threadIdx.x;
    int s0 = blockIdx.y * 128;
    float acc = 0.f;
    #pragma unroll 16
    for (int s = s0; s < s0 + 128; s++)
        acc += g_attn[s] * enc[(size_t)s * H + col];
    g_cpart[blockIdx.y * H + col] = acc;
}

// K4b: sum the 32 partials per column (deterministic). Writes context + y[H:2H].
__global__ void k_ctx_sum(float* __restrict__ out) {
    int col = threadIdx.x;  // 1024 threads
    float acc = 0.f;
    #pragma unroll
    for (int p = 0; p < 32; p++) acc += g_cpart[p * H + col];
    out[OUT_CONTEXT + col] = acc;
    g_y[H + col] = acc;
}

// K5: logits = out_w @ y + out_b. Warp per row, y staged in smem, streaming
// loads on out_w (412 MB, read once — keep it out of L2). THE hot kernel.
__global__ void __launch_bounds__(256) k_logits(const float* __restrict__ out_w,
                                                const float* __restrict__ out_b) {
    __shared__ float4 sy[H2 / 4];
    for (int j = threadIdx.x; j < H2 / 4; j += blockDim.x)
        sy[j] = ((const float4*)g_y)[j];
    __syncthreads();

    int warp = threadIdx.x >> 5, lane = threadIdx.x & 31;
    int row = blockIdx.x * 8 + warp;
    if (row >= V) return;  // whole warp exits together

    const float4* w4 = (const float4*)(out_w + (size_t)row * H2);
    float acc = 0.f;
    #pragma unroll
    for (int i = 0; i < 16; i++) {
        int j = lane + 32 * i;
        acc += dot4(__ldcs(w4 + j), sy[j]);
    }
    acc = warpReduceSum(acc);
    if (lane == 0) g_logits[row] = acc + out_b[row];
}

// K6: log-softmax reduction (single block, 1024 threads).
__global__ void k_lsm_red() {
    __shared__ float sred[32];
    __shared__ float sM, sSum;
    int tid = threadIdx.x;
    int wid = tid >> 5, lane = tid & 31;

    float m = -1e30f;
    for (int i = tid; i < V; i += 1024) m = fmaxf(m, g_logits[i]);
    m = warpReduceMax(m);
    if (lane == 0) sred[wid] = m;
    __syncthreads();
    if (wid == 0) {
        m = sred[lane];
        m = warpReduceMax(m);
        if (lane == 0) sM = m;
    }
    __syncthreads();
    float M = sM;

    float s = 0.f;
    for (int i = tid; i < V; i += 1024) s += expf(g_logits[i] - M);
    s = warpReduceSum(s);
    if (lane == 0) sred[wid] = s;
    __syncthreads();
    if (wid == 0) {
        s = sred[lane];
        s = warpReduceSum(s);
        if (lane == 0) sSum = s;
    }
    __syncthreads();
    if (tid == 0) { g_red[0] = M; g_red[1] = logf(sSum); }
}

// K7: output = logits - max - log(sumexp)
__global__ void k_lsm_write(float* __restrict__ out) {
    int i = blockIdx.x * blockDim.x + threadIdx.x;
    if (i < V) out[OUT_OUTPUT + i] = g_logits[i] - g_red[0] - g_red[1];
}

extern "C" void kernel_launch(void* const* d_in, const int* in_sizes, int n_in,
                              void* d_out, int out_size) {
    const int*   word         = (const int*)d_in[0];
    const float* last_context = (const float*)d_in[1];
    const float* last_hidden  = (const float*)d_in[2];
    const float* enc          = (const float*)d_in[3];
    const float* embedding    = (const float*)d_in[4];
    const float* w_ih         = (const float*)d_in[5];
    const float* w_hh         = (const float*)d_in[6];
    const float* b_ih         = (const float*)d_in[7];
    const float* b_hh         = (const float*)d_in[8];
    const float* out_w        = (const float*)d_in[9];
    const float* out_b        = (const float*)d_in[10];
    float* out = (float*)d_out;

    k_gates    <<<768, 256>>>(word, embedding, last_context, w_ih, w_hh,
                              b_ih, b_hh, last_hidden);
    k_scores   <<<512, 256>>>(enc, last_hidden, out);
    k_softmax  <<<1, 1024>>>(out);
    k_ctx_part <<<dim3(H / 256, 32), 256>>>(enc);
    k_ctx_sum  <<<1, 1024>>>(out);
    k_logits   <<<(V + 7) / 8, 256>>>(out_w, out_b);
    k_lsm_red  <<<1, 1024>>>();
    k_lsm_write<<<(V + 255) / 256, 256>>>(out);
}